// round 9
// baseline (speedup 1.0000x reference)
#include <cuda_runtime.h>
#include <cuda_bf16.h>
#include <cstdint>
#include <cstddef>

constexpr int NN   = 10000;
constexpr int EE   = 320000;
constexpr int DIN  = 512;
constexpr int DOUT = 256;

// ---------------- scratch (__device__ globals; no allocs allowed) ----------
__device__ float g_h[(size_t)NN * DOUT];
__device__ float g_invdeg[NN];
__device__ int   g_degi[NN];
__device__ int   g_off[NN];
__device__ int   g_cur[NN];
__device__ int   g_src[EE];
__device__ int   g_dst[EE];
__device__ int   g_csr[EE];
__device__ int   g_is64;

// bf16 hi/lo split operands
__device__ __nv_bfloat16 g_xhi[(size_t)NN * DIN],  g_xlo[(size_t)NN * DIN];
__device__ __nv_bfloat16 g_w0hi[DIN * DOUT],       g_w0lo[DIN * DOUT];
__device__ __nv_bfloat16 g_wl1hi[DOUT * DOUT],     g_wl1lo[DOUT * DOUT];
__device__ __nv_bfloat16 g_wr1hi[DOUT * DOUT],     g_wr1lo[DOUT * DOUT];
__device__ __nv_bfloat16 g_wl2hi[DOUT * DOUT],     g_wl2lo[DOUT * DOUT];
__device__ __nv_bfloat16 g_wr2hi[DOUT * DOUT],     g_wr2lo[DOUT * DOUT];
__device__ __nv_bfloat16 g_hhi[(size_t)NN * DOUT], g_hlo[(size_t)NN * DOUT];
__device__ __nv_bfloat16 g_mhi[(size_t)NN * DOUT], g_mlo[(size_t)NN * DOUT];
__device__ __nv_bfloat16 g_o1hi[(size_t)NN * DOUT], g_o1lo[(size_t)NN * DOUT];

// ---------------------------------------------------------------------------
// Edge-index dtype detection (int64 vs int32).
// ---------------------------------------------------------------------------
__global__ void detect_kernel(const int* __restrict__ raw) {
    int nz = 0;
    for (int i = threadIdx.x; i < 1024; i += blockDim.x)
        nz |= (raw[2 * i + 1] != 0);
    nz = __syncthreads_or(nz);
    if (threadIdx.x == 0) g_is64 = nz ? 0 : 1;
}

// Decode edge_index into int32 src/dst + in-degree histogram.
__global__ void decode_degi_kernel(const int* __restrict__ raw,
                                   int* __restrict__ src, int* __restrict__ dst,
                                   int* __restrict__ degi) {
    int e = blockIdx.x * blockDim.x + threadIdx.x;
    if (e >= EE) return;
    int s, d;
    if (g_is64) { s = raw[2 * e]; d = raw[2 * (EE + e)]; }
    else        { s = raw[e];     d = raw[EE + e]; }
    src[e] = s;
    dst[e] = d;
    atomicAdd(&degi[d], 1);
}

// ---------------------------------------------------------------------------
// bf16 hi/lo split of x and the five weight matrices (one launch).
// ---------------------------------------------------------------------------
__global__ void split_kernel(const float* __restrict__ x,  const float* __restrict__ W0,
                             const float* __restrict__ Wl1, const float* __restrict__ Wr1,
                             const float* __restrict__ Wl2, const float* __restrict__ Wr2) {
    constexpr int S0 = NN * DIN;
    constexpr int S1 = DIN * DOUT;
    constexpr int S2 = DOUT * DOUT;
    int i = blockIdx.x * blockDim.x + threadIdx.x;
    const float* src; __nv_bfloat16 *hi, *lo; int off;
    if      (i < S0)               { src = x;   hi = g_xhi;  lo = g_xlo;  off = i; }
    else if (i < S0 + S1)          { src = W0;  hi = g_w0hi; lo = g_w0lo; off = i - S0; }
    else if (i < S0 + S1 + S2)     { src = Wl1; hi = g_wl1hi; lo = g_wl1lo; off = i - S0 - S1; }
    else if (i < S0 + S1 + 2 * S2) { src = Wr1; hi = g_wr1hi; lo = g_wr1lo; off = i - S0 - S1 - S2; }
    else if (i < S0 + S1 + 3 * S2) { src = Wl2; hi = g_wl2hi; lo = g_wl2lo; off = i - S0 - S1 - 2 * S2; }
    else if (i < S0 + S1 + 4 * S2) { src = Wr2; hi = g_wr2hi; lo = g_wr2lo; off = i - S0 - S1 - 3 * S2; }
    else return;
    float v = src[off];
    __nv_bfloat16 h = __float2bfloat16(v);
    hi[off] = h;
    lo[off] = __float2bfloat16(v - __bfloat162float(h));
}

// ---------------------------------------------------------------------------
// Exclusive scan over degrees -> CSR offsets + cursors + invdeg (1 block).
// ---------------------------------------------------------------------------
__global__ void scan_kernel(const int* __restrict__ degi, int* __restrict__ off,
                            int* __restrict__ cur, float* __restrict__ invdeg) {
    __shared__ int part[256];
    const int t = threadIdx.x;
    const int CH = (NN + 255) / 256;
    const int s0 = t * CH;
    int sum = 0;
    for (int j = 0; j < CH; j++) { int i = s0 + j; if (i < NN) sum += degi[i]; }
    part[t] = sum;
    __syncthreads();
    for (int d = 1; d < 256; d <<= 1) {
        int v = (t >= d) ? part[t - d] : 0;
        __syncthreads();
        part[t] += v;
        __syncthreads();
    }
    int run = (t > 0) ? part[t - 1] : 0;
    for (int j = 0; j < CH; j++) {
        int i = s0 + j;
        if (i < NN) {
            off[i] = run; cur[i] = run;
            int d = degi[i]; run += d;
            invdeg[i] = 1.0f / fmaxf((float)d, 1.0f);
        }
    }
}

__global__ void fill_kernel(const int* __restrict__ src, const int* __restrict__ dst,
                            int* __restrict__ cur, int* __restrict__ csr) {
    int e = blockIdx.x * blockDim.x + threadIdx.x;
    if (e < EE) {
        int p = atomicAdd(&cur[dst[e]], 1);
        csr[p] = src[e];
    }
}

// ---------------------------------------------------------------------------
// CSR gather: mean[i] = invdeg_i * sum h[src(e)], emitted as bf16 hi/lo.
// ---------------------------------------------------------------------------
__global__ void gather_kernel(const float* __restrict__ h,
                              const int* __restrict__ csr,
                              const int* __restrict__ off,
                              const int* __restrict__ degi,
                              const float* __restrict__ invdeg,
                              __nv_bfloat16* __restrict__ mhi,
                              __nv_bfloat16* __restrict__ mlo) {
    const int node = blockIdx.x;
    const int t = threadIdx.x;               // 0..63
    const int base = off[node];
    const int n = degi[node];
    const float4* hp = (const float4*)h;
    float4 acc = make_float4(0.f, 0.f, 0.f, 0.f);
    int e = 0;
    for (; e + 4 <= n; e += 4) {
        int s0 = csr[base + e + 0];
        int s1 = csr[base + e + 1];
        int s2 = csr[base + e + 2];
        int s3 = csr[base + e + 3];
        float4 v0 = hp[(size_t)s0 * 64 + t];
        float4 v1 = hp[(size_t)s1 * 64 + t];
        float4 v2 = hp[(size_t)s2 * 64 + t];
        float4 v3 = hp[(size_t)s3 * 64 + t];
        acc.x += (v0.x + v1.x) + (v2.x + v3.x);
        acc.y += (v0.y + v1.y) + (v2.y + v3.y);
        acc.z += (v0.z + v1.z) + (v2.z + v3.z);
        acc.w += (v0.w + v1.w) + (v2.w + v3.w);
    }
    for (; e < n; e++) {
        int s = csr[base + e];
        float4 v = hp[(size_t)s * 64 + t];
        acc.x += v.x; acc.y += v.y; acc.z += v.z; acc.w += v.w;
    }
    const float s = invdeg[node];
    float o[4] = {acc.x * s, acc.y * s, acc.z * s, acc.w * s};
    __nv_bfloat16 hi[4], lo[4];
#pragma unroll
    for (int j = 0; j < 4; j++) {
        hi[j] = __float2bfloat16(o[j]);
        lo[j] = __float2bfloat16(o[j] - __bfloat162float(hi[j]));
    }
    size_t p = (size_t)node * DOUT + t * 4;
    __nv_bfloat162 a, b;
    a.x = hi[0]; a.y = hi[1]; b.x = hi[2]; b.y = hi[3];
    *(__nv_bfloat162*)(mhi + p) = a; *(__nv_bfloat162*)(mhi + p + 2) = b;
    a.x = lo[0]; a.y = lo[1]; b.x = lo[2]; b.y = lo[3];
    *(__nv_bfloat162*)(mlo + p) = a; *(__nv_bfloat162*)(mlo + p + 2) = b;
}

// ---------------------------------------------------------------------------
// Tensor-core GEMM (bf16x3 split), cp.async 4-stage + register fragment
// double-buffering: ldmatrix for stage s+1 overlaps the 32 MMAs of stage s.
// Block 64x64, 4 warps (32x32 warp tile), BK=32, single barrier per stage.
// ---------------------------------------------------------------------------
struct PassList {
    const __nv_bfloat16* A[6];
    const __nv_bfloat16* W[6];
};

#define LDSM4(d, addr) \
    asm volatile("ldmatrix.sync.aligned.m8n8.x4.shared.b16 {%0,%1,%2,%3}, [%4];" \
        : "=r"(d[0]), "=r"(d[1]), "=r"(d[2]), "=r"(d[3]) : "r"(addr))
#define LDSM4T(d, addr) \
    asm volatile("ldmatrix.sync.aligned.m8n8.x4.trans.shared.b16 {%0,%1,%2,%3}, [%4];" \
        : "=r"(d[0]), "=r"(d[1]), "=r"(d[2]), "=r"(d[3]) : "r"(addr))
#define MMA16816(c, a, b0, b1) \
    asm volatile("mma.sync.aligned.m16n8k16.row.col.f32.bf16.bf16.f32 " \
        "{%0,%1,%2,%3}, {%4,%5,%6,%7}, {%8,%9}, {%0,%1,%2,%3};" \
        : "+f"(c[0]), "+f"(c[1]), "+f"(c[2]), "+f"(c[3]) \
        : "r"(a[0]), "r"(a[1]), "r"(a[2]), "r"(a[3]), "r"(b0), "r"(b1))
#define CPA16(dst, src, sz) \
    asm volatile("cp.async.cg.shared.global [%0], [%1], 16, %2;" \
        :: "r"(dst), "l"(src), "r"(sz))
#define CPA_COMMIT() asm volatile("cp.async.commit_group;")

constexpr int ASTR = 40;          // halfs; 80B row stride (conflict-free ldsm)
constexpr int WSTR = 72;          // halfs; 144B row stride (conflict-free ldsm)
constexpr int ABUF = 64 * ASTR;   // halfs per A stage buffer
constexpr int WBUF = 32 * WSTR;   // halfs per W stage buffer
constexpr int PIPE = 4;

template<int K, int NP, bool RELU, bool RES, bool OUTS>
__global__ __launch_bounds__(128)
void gemm_mma(PassList P, const float* __restrict__ bias, const float* __restrict__ res,
              float* __restrict__ C, __nv_bfloat16* __restrict__ Chi,
              __nv_bfloat16* __restrict__ Clo, int M) {
    constexpr int KS = K / 32;
    constexpr int NST = NP * KS;       // >= 24
    __shared__ __align__(16) __nv_bfloat16 As[PIPE * ABUF];
    __shared__ __align__(16) __nv_bfloat16 Ws[PIPE * WBUF];

    const int tid = threadIdx.x, wid = tid >> 5, lane = tid & 31;
    const int row0 = blockIdx.y * 64, col0 = blockIdx.x * 64;
    const int mb = (wid & 1) * 32, nb = (wid >> 1) * 32;

    float acc[2][4][4];
#pragma unroll
    for (int mt = 0; mt < 2; mt++)
#pragma unroll
        for (int nt = 0; nt < 4; nt++)
#pragma unroll
            for (int r = 0; r < 4; r++) acc[mt][nt][r] = 0.f;

    // cp.async mapping (128 threads)
    const int arow = tid >> 2;
    const int achunk = (tid & 3) * 8;
    const int wk = tid >> 2;
    const int wn = (tid & 3) * 16;

    const uint32_t asu = (uint32_t)__cvta_generic_to_shared(As);
    const uint32_t wsu = (uint32_t)__cvta_generic_to_shared(Ws);

    const int r0g = row0 + arow, r1g = r0g + 32;
    const int sz0 = (r0g < M) ? 16 : 0, sz1 = (r1g < M) ? 16 : 0;
    const int r0c = (r0g < M) ? r0g : 0, r1c = (r1g < M) ? r1g : 0;

#define ISSUE(S, BUF) { \
        const int pass = (S) / KS; const int k0 = ((S) - pass * KS) * 32; \
        const __nv_bfloat16* Ap = P.A[pass]; const __nv_bfloat16* Wp = P.W[pass]; \
        CPA16(asu + ((BUF) * ABUF + arow * ASTR + achunk) * 2, \
              Ap + (size_t)r0c * K + k0 + achunk, sz0); \
        CPA16(asu + ((BUF) * ABUF + (arow + 32) * ASTR + achunk) * 2, \
              Ap + (size_t)r1c * K + k0 + achunk, sz1); \
        CPA16(wsu + ((BUF) * WBUF + wk * WSTR + wn) * 2, \
              Wp + (size_t)(k0 + wk) * DOUT + col0 + wn, 16); \
        CPA16(wsu + ((BUF) * WBUF + wk * WSTR + wn + 8) * 2, \
              Wp + (size_t)(k0 + wk) * DOUT + col0 + wn + 8, 16); \
        CPA_COMMIT(); \
    }

    const int r = lane & 7, selr = lane >> 3;
    const uint32_t aoff = (uint32_t)((mb + (selr & 1) * 8 + r) * ASTR + (selr >> 1) * 8) * 2;
    const uint32_t boff = (uint32_t)(((selr & 1) * 8 + r) * WSTR + nb + (selr >> 1) * 8) * 2;

    // fragment ring: [ring][kk2*2 + mt/grp][4]
    uint32_t fa[2][4][4], fb[2][4][4];

#define LDFRAG(RING, BUF) { \
        const uint32_t abase = asu + (BUF) * ABUF * 2 + aoff; \
        const uint32_t wbase = wsu + (BUF) * WBUF * 2 + boff; \
        LDSM4(fa[RING][0], abase); \
        LDSM4(fa[RING][1], abase + 16 * ASTR * 2); \
        LDSM4T(fb[RING][0], wbase); \
        LDSM4T(fb[RING][1], wbase + 16 * 2); \
        LDSM4(fa[RING][2], abase + 32); \
        LDSM4(fa[RING][3], abase + 32 + 16 * ASTR * 2); \
        LDSM4T(fb[RING][2], wbase + 16 * WSTR * 2); \
        LDSM4T(fb[RING][3], wbase + 16 * WSTR * 2 + 16 * 2); \
    }

#define MMASTAGE(RING) { \
        _Pragma("unroll") \
        for (int kk2 = 0; kk2 < 2; kk2++) { \
            _Pragma("unroll") \
            for (int mt = 0; mt < 2; mt++) { \
                MMA16816(acc[mt][0], fa[RING][kk2 * 2 + mt], fb[RING][kk2 * 2][0], fb[RING][kk2 * 2][1]); \
                MMA16816(acc[mt][1], fa[RING][kk2 * 2 + mt], fb[RING][kk2 * 2][2], fb[RING][kk2 * 2][3]); \
                MMA16816(acc[mt][2], fa[RING][kk2 * 2 + mt], fb[RING][kk2 * 2 + 1][0], fb[RING][kk2 * 2 + 1][1]); \
                MMA16816(acc[mt][3], fa[RING][kk2 * 2 + mt], fb[RING][kk2 * 2 + 1][2], fb[RING][kk2 * 2 + 1][3]); \
            } \
        } \
    }

    // prologue: stages 0..2 in flight; frags of stage 0 in registers
    ISSUE(0, 0); ISSUE(1, 1); ISSUE(2, 2);
    asm volatile("cp.async.wait_group 2;");
    __syncthreads();
    LDFRAG(0, 0);

    for (int s = 0; s < NST; s++) {
        if (s + 3 < NST) ISSUE(s + 3, (s + 3) % PIPE);
        if (s + 1 < NST) {
            // pending groups after the one we need = min(NST-1, s+3) - (s+1)
            if (s + 3 < NST)      asm volatile("cp.async.wait_group 2;");
            else if (s + 2 < NST) asm volatile("cp.async.wait_group 1;");
            else                  asm volatile("cp.async.wait_group 0;");
            __syncthreads();
            LDFRAG((s + 1) & 1, (s + 1) % PIPE);
        }
        MMASTAGE(s & 1);
    }
#undef ISSUE
#undef LDFRAG
#undef MMASTAGE

    // epilogue
    const int g = lane >> 2, tig = lane & 3;
#pragma unroll
    for (int mt = 0; mt < 2; mt++) {
#pragma unroll
        for (int half = 0; half < 2; half++) {
            const int row = row0 + mb + mt * 16 + g + half * 8;
            if (row >= M) continue;
#pragma unroll
            for (int nt = 0; nt < 4; nt++) {
                const int col = col0 + nb + nt * 8 + tig * 2;
                float v0 = acc[mt][nt][half * 2 + 0] + bias[col];
                float v1 = acc[mt][nt][half * 2 + 1] + bias[col + 1];
                if (RELU) { v0 = fmaxf(v0, 0.f); v1 = fmaxf(v1, 0.f); }
                if (RES) {
                    float2 rr = *(const float2*)(res + (size_t)row * DOUT + col);
                    v0 += rr.x; v1 += rr.y;
                }
                float2 o; o.x = v0; o.y = v1;
                *(float2*)(C + (size_t)row * DOUT + col) = o;
                if (OUTS) {
                    __nv_bfloat16 h0 = __float2bfloat16(v0), h1 = __float2bfloat16(v1);
                    __nv_bfloat162 hh; hh.x = h0; hh.y = h1;
                    *(__nv_bfloat162*)(Chi + (size_t)row * DOUT + col) = hh;
                    __nv_bfloat162 ll;
                    ll.x = __float2bfloat16(v0 - __bfloat162float(h0));
                    ll.y = __float2bfloat16(v1 - __bfloat162float(h1));
                    *(__nv_bfloat162*)(Clo + (size_t)row * DOUT + col) = ll;
                }
            }
        }
    }
}

// ---------------------------------------------------------------------------
// Launch: detect(1) decode(2) split(3) gemm1(4=capture) scan fill
//         gather gemm2 gather gemm3
// ---------------------------------------------------------------------------
extern "C" void kernel_launch(void* const* d_in, const int* in_sizes, int n_in,
                              void* d_out, int out_size) {
    const float* x   = (const float*)d_in[0];
    const int*   ei  = (const int*)d_in[1];
    const float* W0  = (const float*)d_in[2];
    const float* b0  = (const float*)d_in[3];
    const float* Wl1 = (const float*)d_in[4];
    const float* bl1 = (const float*)d_in[5];
    const float* Wr1 = (const float*)d_in[6];
    const float* Wl2 = (const float*)d_in[7];
    const float* bl2 = (const float*)d_in[8];
    const float* Wr2 = (const float*)d_in[9];

    float* out1 = (float*)d_out;
    float* out2 = out1 + (size_t)NN * DOUT;

    float *h, *invdeg;
    int *degi, *off, *cur, *src, *dst, *csr;
    __nv_bfloat16 *xhi, *xlo, *w0hi, *w0lo, *wl1hi, *wl1lo, *wr1hi, *wr1lo;
    __nv_bfloat16 *wl2hi, *wl2lo, *wr2hi, *wr2lo, *hhi, *hlo, *mhi, *mlo, *o1hi, *o1lo;
    cudaGetSymbolAddress((void**)&h,      g_h);
    cudaGetSymbolAddress((void**)&invdeg, g_invdeg);
    cudaGetSymbolAddress((void**)&degi,   g_degi);
    cudaGetSymbolAddress((void**)&off,    g_off);
    cudaGetSymbolAddress((void**)&cur,    g_cur);
    cudaGetSymbolAddress((void**)&src,    g_src);
    cudaGetSymbolAddress((void**)&dst,    g_dst);
    cudaGetSymbolAddress((void**)&csr,    g_csr);
    cudaGetSymbolAddress((void**)&xhi,   g_xhi);   cudaGetSymbolAddress((void**)&xlo,   g_xlo);
    cudaGetSymbolAddress((void**)&w0hi,  g_w0hi);  cudaGetSymbolAddress((void**)&w0lo,  g_w0lo);
    cudaGetSymbolAddress((void**)&wl1hi, g_wl1hi); cudaGetSymbolAddress((void**)&wl1lo, g_wl1lo);
    cudaGetSymbolAddress((void**)&wr1hi, g_wr1hi); cudaGetSymbolAddress((void**)&wr1lo, g_wr1lo);
    cudaGetSymbolAddress((void**)&wl2hi, g_wl2hi); cudaGetSymbolAddress((void**)&wl2lo, g_wl2lo);
    cudaGetSymbolAddress((void**)&wr2hi, g_wr2hi); cudaGetSymbolAddress((void**)&wr2lo, g_wr2lo);
    cudaGetSymbolAddress((void**)&hhi,   g_hhi);   cudaGetSymbolAddress((void**)&hlo,   g_hlo);
    cudaGetSymbolAddress((void**)&mhi,   g_mhi);   cudaGetSymbolAddress((void**)&mlo,   g_mlo);
    cudaGetSymbolAddress((void**)&o1hi,  g_o1hi);  cudaGetSymbolAddress((void**)&o1lo,  g_o1lo);

    const int EB = (EE + 255) / 256;
    const int SPLIT_N = NN * DIN + DIN * DOUT + 4 * DOUT * DOUT;
    dim3 mgrid(DOUT / 64, (NN + 63) / 64);    // (4, 157) = 628 blocks

    detect_kernel<<<1, 256>>>(ei);                                     // k1
    cudaMemsetAsync(degi, 0, NN * sizeof(int));
    decode_degi_kernel<<<EB, 256>>>(ei, src, dst, degi);               // k2
    split_kernel<<<(SPLIT_N + 255) / 256, 256>>>(x, W0, Wl1, Wr1, Wl2, Wr2);  // k3

    // gemm1: h = x @ W0 + b0  (bf16x3: 3 passes, K=512) — k4, capture target
    {
        PassList P{};
        P.A[0] = xhi; P.W[0] = w0hi;
        P.A[1] = xlo; P.W[1] = w0hi;
        P.A[2] = xhi; P.W[2] = w0lo;
        gemm_mma<DIN, 3, false, false, true><<<mgrid, 128>>>(
            P, b0, nullptr, h, hhi, hlo, NN);
    }

    scan_kernel<<<1, 256>>>(degi, off, cur, invdeg);                   // k5
    fill_kernel<<<EB, 256>>>(src, dst, cur, csr);                      // k6

    // conv1
    gather_kernel<<<NN, 64>>>(h, csr, off, degi, invdeg, mhi, mlo);
    {
        PassList P{};
        P.A[0] = mhi; P.W[0] = wl1hi;
        P.A[1] = mlo; P.W[1] = wl1hi;
        P.A[2] = mhi; P.W[2] = wl1lo;
        P.A[3] = hhi; P.W[3] = wr1hi;
        P.A[4] = hlo; P.W[4] = wr1hi;
        P.A[5] = hhi; P.W[5] = wr1lo;
        gemm_mma<DOUT, 6, true, true, true><<<mgrid, 128>>>(
            P, bl1, h, out1, o1hi, o1lo, NN);
    }

    // conv2
    gather_kernel<<<NN, 64>>>(out1, csr, off, degi, invdeg, mhi, mlo);
    {
        PassList P{};
        P.A[0] = mhi;  P.W[0] = wl2hi;
        P.A[1] = mlo;  P.W[1] = wl2hi;
        P.A[2] = mhi;  P.W[2] = wl2lo;
        P.A[3] = o1hi; P.W[3] = wr2hi;
        P.A[4] = o1lo; P.W[4] = wr2hi;
        P.A[5] = o1hi; P.W[5] = wr2lo;
        gemm_mma<DOUT, 6, false, true, false><<<mgrid, 128>>>(
            P, bl2, out1, out2, nullptr, nullptr, NN);
    }
}

// round 10
// speedup vs baseline: 1.0364x; 1.0364x over previous
#include <cuda_runtime.h>
#include <cuda_bf16.h>
#include <cstdint>
#include <cstddef>

constexpr int NN   = 10000;
constexpr int EE   = 320000;
constexpr int DIN  = 512;
constexpr int DOUT = 256;

// ---------------- scratch (__device__ globals; no allocs allowed) ----------
__device__ float g_h[(size_t)NN * DOUT];
__device__ float g_invdeg[NN];
__device__ int   g_degi[NN];
__device__ int   g_off[NN];
__device__ int   g_cur[NN];
__device__ int   g_src[EE];
__device__ int   g_dst[EE];
__device__ int   g_csr[EE];
__device__ int   g_is64;

// bf16 hi/lo split operands
__device__ __nv_bfloat16 g_xhi[(size_t)NN * DIN],  g_xlo[(size_t)NN * DIN];
__device__ __nv_bfloat16 g_w0hi[DIN * DOUT],       g_w0lo[DIN * DOUT];
__device__ __nv_bfloat16 g_wl1hi[DOUT * DOUT],     g_wl1lo[DOUT * DOUT];
__device__ __nv_bfloat16 g_wr1hi[DOUT * DOUT],     g_wr1lo[DOUT * DOUT];
__device__ __nv_bfloat16 g_wl2hi[DOUT * DOUT],     g_wl2lo[DOUT * DOUT];
__device__ __nv_bfloat16 g_wr2hi[DOUT * DOUT],     g_wr2lo[DOUT * DOUT];
__device__ __nv_bfloat16 g_hhi[(size_t)NN * DOUT], g_hlo[(size_t)NN * DOUT];
__device__ __nv_bfloat16 g_mhi[(size_t)NN * DOUT], g_mlo[(size_t)NN * DOUT];
__device__ __nv_bfloat16 g_o1hi[(size_t)NN * DOUT], g_o1lo[(size_t)NN * DOUT];

// ---------------------------------------------------------------------------
// Edge-index dtype detection (int64 vs int32).
// ---------------------------------------------------------------------------
__global__ void detect_kernel(const int* __restrict__ raw) {
    int nz = 0;
    for (int i = threadIdx.x; i < 1024; i += blockDim.x)
        nz |= (raw[2 * i + 1] != 0);
    nz = __syncthreads_or(nz);
    if (threadIdx.x == 0) g_is64 = nz ? 0 : 1;
}

// Decode edge_index into int32 src/dst + in-degree histogram.
__global__ void decode_degi_kernel(const int* __restrict__ raw,
                                   int* __restrict__ src, int* __restrict__ dst,
                                   int* __restrict__ degi) {
    int e = blockIdx.x * blockDim.x + threadIdx.x;
    if (e >= EE) return;
    int s, d;
    if (g_is64) { s = raw[2 * e]; d = raw[2 * (EE + e)]; }
    else        { s = raw[e];     d = raw[EE + e]; }
    src[e] = s;
    dst[e] = d;
    atomicAdd(&degi[d], 1);
}

// ---------------------------------------------------------------------------
// bf16 hi/lo split of x and the five weight matrices (one launch).
// ---------------------------------------------------------------------------
__global__ void split_kernel(const float* __restrict__ x,  const float* __restrict__ W0,
                             const float* __restrict__ Wl1, const float* __restrict__ Wr1,
                             const float* __restrict__ Wl2, const float* __restrict__ Wr2) {
    constexpr int S0 = NN * DIN;
    constexpr int S1 = DIN * DOUT;
    constexpr int S2 = DOUT * DOUT;
    int i = blockIdx.x * blockDim.x + threadIdx.x;
    const float* src; __nv_bfloat16 *hi, *lo; int off;
    if      (i < S0)               { src = x;   hi = g_xhi;  lo = g_xlo;  off = i; }
    else if (i < S0 + S1)          { src = W0;  hi = g_w0hi; lo = g_w0lo; off = i - S0; }
    else if (i < S0 + S1 + S2)     { src = Wl1; hi = g_wl1hi; lo = g_wl1lo; off = i - S0 - S1; }
    else if (i < S0 + S1 + 2 * S2) { src = Wr1; hi = g_wr1hi; lo = g_wr1lo; off = i - S0 - S1 - S2; }
    else if (i < S0 + S1 + 3 * S2) { src = Wl2; hi = g_wl2hi; lo = g_wl2lo; off = i - S0 - S1 - 2 * S2; }
    else if (i < S0 + S1 + 4 * S2) { src = Wr2; hi = g_wr2hi; lo = g_wr2lo; off = i - S0 - S1 - 3 * S2; }
    else return;
    float v = src[off];
    __nv_bfloat16 h = __float2bfloat16(v);
    hi[off] = h;
    lo[off] = __float2bfloat16(v - __bfloat162float(h));
}

// ---------------------------------------------------------------------------
// Exclusive scan over degrees -> CSR offsets + cursors + invdeg (1 block).
// ---------------------------------------------------------------------------
__global__ void scan_kernel(const int* __restrict__ degi, int* __restrict__ off,
                            int* __restrict__ cur, float* __restrict__ invdeg) {
    __shared__ int part[256];
    const int t = threadIdx.x;
    const int CH = (NN + 255) / 256;
    const int s0 = t * CH;
    int sum = 0;
    for (int j = 0; j < CH; j++) { int i = s0 + j; if (i < NN) sum += degi[i]; }
    part[t] = sum;
    __syncthreads();
    for (int d = 1; d < 256; d <<= 1) {
        int v = (t >= d) ? part[t - d] : 0;
        __syncthreads();
        part[t] += v;
        __syncthreads();
    }
    int run = (t > 0) ? part[t - 1] : 0;
    for (int j = 0; j < CH; j++) {
        int i = s0 + j;
        if (i < NN) {
            off[i] = run; cur[i] = run;
            int d = degi[i]; run += d;
            invdeg[i] = 1.0f / fmaxf((float)d, 1.0f);
        }
    }
}

__global__ void fill_kernel(const int* __restrict__ src, const int* __restrict__ dst,
                            int* __restrict__ cur, int* __restrict__ csr) {
    int e = blockIdx.x * blockDim.x + threadIdx.x;
    if (e < EE) {
        int p = atomicAdd(&cur[dst[e]], 1);
        csr[p] = src[e];
    }
}

// ---------------------------------------------------------------------------
// CSR gather: mean[i] = invdeg_i * sum h[src(e)], emitted as bf16 hi/lo.
// ---------------------------------------------------------------------------
__global__ void gather_kernel(const float* __restrict__ h,
                              const int* __restrict__ csr,
                              const int* __restrict__ off,
                              const int* __restrict__ degi,
                              const float* __restrict__ invdeg,
                              __nv_bfloat16* __restrict__ mhi,
                              __nv_bfloat16* __restrict__ mlo) {
    const int node = blockIdx.x;
    const int t = threadIdx.x;               // 0..63
    const int base = off[node];
    const int n = degi[node];
    const float4* hp = (const float4*)h;
    float4 acc = make_float4(0.f, 0.f, 0.f, 0.f);
    int e = 0;
    for (; e + 4 <= n; e += 4) {
        int s0 = csr[base + e + 0];
        int s1 = csr[base + e + 1];
        int s2 = csr[base + e + 2];
        int s3 = csr[base + e + 3];
        float4 v0 = hp[(size_t)s0 * 64 + t];
        float4 v1 = hp[(size_t)s1 * 64 + t];
        float4 v2 = hp[(size_t)s2 * 64 + t];
        float4 v3 = hp[(size_t)s3 * 64 + t];
        acc.x += (v0.x + v1.x) + (v2.x + v3.x);
        acc.y += (v0.y + v1.y) + (v2.y + v3.y);
        acc.z += (v0.z + v1.z) + (v2.z + v3.z);
        acc.w += (v0.w + v1.w) + (v2.w + v3.w);
    }
    for (; e < n; e++) {
        int s = csr[base + e];
        float4 v = hp[(size_t)s * 64 + t];
        acc.x += v.x; acc.y += v.y; acc.z += v.z; acc.w += v.w;
    }
    const float s = invdeg[node];
    float o[4] = {acc.x * s, acc.y * s, acc.z * s, acc.w * s};
    __nv_bfloat16 hi[4], lo[4];
#pragma unroll
    for (int j = 0; j < 4; j++) {
        hi[j] = __float2bfloat16(o[j]);
        lo[j] = __float2bfloat16(o[j] - __bfloat162float(hi[j]));
    }
    size_t p = (size_t)node * DOUT + t * 4;
    __nv_bfloat162 a, b;
    a.x = hi[0]; a.y = hi[1]; b.x = hi[2]; b.y = hi[3];
    *(__nv_bfloat162*)(mhi + p) = a; *(__nv_bfloat162*)(mhi + p + 2) = b;
    a.x = lo[0]; a.y = lo[1]; b.x = lo[2]; b.y = lo[3];
    *(__nv_bfloat162*)(mlo + p) = a; *(__nv_bfloat162*)(mlo + p + 2) = b;
}

// ---------------------------------------------------------------------------
// Tensor-core GEMM (bf16x3 split), cp.async pipelined, IN-BLOCK SPLIT-K:
// 256 threads = 2 warp-groups of 4 warps; group g processes K-stages
// [g*NST/2, (g+1)*NST/2) on its own smem ring with its own named barrier.
// Final: group 1 dumps accumulators to smem; group 0 adds + epilogue.
// Block tile 64x64, warp tile 32x32, BK=32, mma.sync m16n8k16 bf16->f32.
// ---------------------------------------------------------------------------
struct PassList {
    const __nv_bfloat16* A[6];
    const __nv_bfloat16* W[6];
};

#define LDSM4(d0, d1, d2, d3, addr) \
    asm volatile("ldmatrix.sync.aligned.m8n8.x4.shared.b16 {%0,%1,%2,%3}, [%4];" \
        : "=r"(d0), "=r"(d1), "=r"(d2), "=r"(d3) : "r"(addr))
#define LDSM4T(d0, d1, d2, d3, addr) \
    asm volatile("ldmatrix.sync.aligned.m8n8.x4.trans.shared.b16 {%0,%1,%2,%3}, [%4];" \
        : "=r"(d0), "=r"(d1), "=r"(d2), "=r"(d3) : "r"(addr))
#define MMA16816(c, a, b0, b1) \
    asm volatile("mma.sync.aligned.m16n8k16.row.col.f32.bf16.bf16.f32 " \
        "{%0,%1,%2,%3}, {%4,%5,%6,%7}, {%8,%9}, {%0,%1,%2,%3};" \
        : "+f"(c[0]), "+f"(c[1]), "+f"(c[2]), "+f"(c[3]) \
        : "r"(a[0]), "r"(a[1]), "r"(a[2]), "r"(a[3]), "r"(b0), "r"(b1))
#define CPA16(dst, src, sz) \
    asm volatile("cp.async.cg.shared.global [%0], [%1], 16, %2;" \
        :: "r"(dst), "l"(src), "r"(sz))
#define CPA_COMMIT() asm volatile("cp.async.commit_group;")
#define GBAR(id) asm volatile("bar.sync %0, 128;" :: "r"(id) : "memory")

constexpr int ASTR = 40;          // halfs; 80B row stride (conflict-free ldsm)
constexpr int WSTR = 72;          // halfs; 144B row stride (conflict-free ldsm)
constexpr int ABUF = 64 * ASTR;   // halfs per A stage buffer
constexpr int WBUF = 32 * WSTR;   // halfs per W stage buffer
constexpr int PIPE = 3;

template<int K, int NP, bool RELU, bool RES, bool OUTS>
__global__ __launch_bounds__(256)
void gemm_mma(PassList P, const float* __restrict__ bias, const float* __restrict__ res,
              float* __restrict__ C, __nv_bfloat16* __restrict__ Chi,
              __nv_bfloat16* __restrict__ Clo, int M) {
    constexpr int KS = K / 32;
    constexpr int NST = NP * KS;       // 48 for both shapes
    constexpr int HALF = NST / 2;      // 24
    __shared__ __align__(16) __nv_bfloat16 As[2 * PIPE * ABUF];
    __shared__ __align__(16) __nv_bfloat16 Ws[2 * PIPE * WBUF];

    const int tid = threadIdx.x;
    const int group = tid >> 7;         // 0 or 1
    const int gtid = tid & 127;
    const int gwid = gtid >> 5;         // warp within group, 0..3
    const int lane = tid & 31;
    const int row0 = blockIdx.y * 64, col0 = blockIdx.x * 64;
    const int mb = (gwid & 1) * 32, nb = (gwid >> 1) * 32;

    float acc[2][4][4];
#pragma unroll
    for (int mt = 0; mt < 2; mt++)
#pragma unroll
        for (int nt = 0; nt < 4; nt++)
#pragma unroll
            for (int r = 0; r < 4; r++) acc[mt][nt][r] = 0.f;

    // cp.async mapping within a 128-thread group
    const int arow = gtid >> 2;
    const int achunk = (gtid & 3) * 8;
    const int wk = gtid >> 2;
    const int wn = (gtid & 3) * 16;

    const uint32_t asu = (uint32_t)__cvta_generic_to_shared(As) + group * PIPE * ABUF * 2;
    const uint32_t wsu = (uint32_t)__cvta_generic_to_shared(Ws) + group * PIPE * WBUF * 2;

    const int r0g = row0 + arow, r1g = r0g + 32;
    const int sz0 = (r0g < M) ? 16 : 0, sz1 = (r1g < M) ? 16 : 0;
    const int r0c = (r0g < M) ? r0g : 0, r1c = (r1g < M) ? r1g : 0;

#define ISSUE(S, BUF) { \
        const int pass = (S) / KS; const int k0 = ((S) - pass * KS) * 32; \
        const __nv_bfloat16* Ap = P.A[pass]; const __nv_bfloat16* Wp = P.W[pass]; \
        CPA16(asu + ((BUF) * ABUF + arow * ASTR + achunk) * 2, \
              Ap + (size_t)r0c * K + k0 + achunk, sz0); \
        CPA16(asu + ((BUF) * ABUF + (arow + 32) * ASTR + achunk) * 2, \
              Ap + (size_t)r1c * K + k0 + achunk, sz1); \
        CPA16(wsu + ((BUF) * WBUF + wk * WSTR + wn) * 2, \
              Wp + (size_t)(k0 + wk) * DOUT + col0 + wn, 16); \
        CPA16(wsu + ((BUF) * WBUF + wk * WSTR + wn + 8) * 2, \
              Wp + (size_t)(k0 + wk) * DOUT + col0 + wn + 8, 16); \
        CPA_COMMIT(); \
    }

    const int gs0 = group * HALF;
    ISSUE(gs0 + 0, 0);
    ISSUE(gs0 + 1, 1);

    const int r = lane & 7, selr = lane >> 3;
    const uint32_t aoff = (uint32_t)((mb + (selr & 1) * 8 + r) * ASTR + (selr >> 1) * 8) * 2;
    const uint32_t boff = (uint32_t)(((selr & 1) * 8 + r) * WSTR + nb + (selr >> 1) * 8) * 2;

    for (int i = 0; i < HALF; i++) {
        if (i + 1 < HALF) { asm volatile("cp.async.wait_group 1;"); }
        else              { asm volatile("cp.async.wait_group 0;"); }
        GBAR(group + 1);
        // Safe: buffer (i+2)%3 == (i-1)%3, whose readers all passed this barrier.
        if (i + 2 < HALF) ISSUE(gs0 + i + 2, (i + 2) % PIPE);

        const int buf = i % PIPE;
        const uint32_t abase = asu + buf * ABUF * 2 + aoff;
        const uint32_t wbase = wsu + buf * WBUF * 2 + boff;
#pragma unroll
        for (int kk = 0; kk < 32; kk += 16) {
            uint32_t a[2][4], bt0[4], bt1[4];
            uint32_t aaddr = abase + kk * 2;
            LDSM4(a[0][0], a[0][1], a[0][2], a[0][3], aaddr);
            LDSM4(a[1][0], a[1][1], a[1][2], a[1][3], aaddr + 16 * ASTR * 2);
            uint32_t baddr = wbase + kk * WSTR * 2;
            LDSM4T(bt0[0], bt0[1], bt0[2], bt0[3], baddr);
            LDSM4T(bt1[0], bt1[1], bt1[2], bt1[3], baddr + 16 * 2);
#pragma unroll
            for (int mt = 0; mt < 2; mt++) {
                MMA16816(acc[mt][0], a[mt], bt0[0], bt0[1]);
                MMA16816(acc[mt][1], a[mt], bt0[2], bt0[3]);
                MMA16816(acc[mt][2], a[mt], bt1[0], bt1[1]);
                MMA16816(acc[mt][3], a[mt], bt1[2], bt1[3]);
            }
        }
    }
#undef ISSUE

    // ---- combine the two K-halves: group1 -> smem -> group0 adds ----
    __syncthreads();
    float* pbuf = reinterpret_cast<float*>(As);   // 128*32*4 = 16 KB, fits in As
    float* af = &acc[0][0][0];
    if (group == 1) {
#pragma unroll
        for (int i = 0; i < 32; i++) pbuf[i * 128 + gtid] = af[i];
    }
    __syncthreads();
    if (group == 1) return;
#pragma unroll
    for (int i = 0; i < 32; i++) af[i] += pbuf[i * 128 + gtid];

    // epilogue (group 0 only; exact fp32 2-way sum -> deterministic)
    const int g = lane >> 2, tig = lane & 3;
#pragma unroll
    for (int mt = 0; mt < 2; mt++) {
#pragma unroll
        for (int half = 0; half < 2; half++) {
            const int row = row0 + mb + mt * 16 + g + half * 8;
            if (row >= M) continue;
#pragma unroll
            for (int nt = 0; nt < 4; nt++) {
                const int col = col0 + nb + nt * 8 + tig * 2;
                float v0 = acc[mt][nt][half * 2 + 0] + bias[col];
                float v1 = acc[mt][nt][half * 2 + 1] + bias[col + 1];
                if (RELU) { v0 = fmaxf(v0, 0.f); v1 = fmaxf(v1, 0.f); }
                if (RES) {
                    float2 rr = *(const float2*)(res + (size_t)row * DOUT + col);
                    v0 += rr.x; v1 += rr.y;
                }
                float2 o; o.x = v0; o.y = v1;
                *(float2*)(C + (size_t)row * DOUT + col) = o;
                if (OUTS) {
                    __nv_bfloat16 h0 = __float2bfloat16(v0), h1 = __float2bfloat16(v1);
                    __nv_bfloat162 hh; hh.x = h0; hh.y = h1;
                    *(__nv_bfloat162*)(Chi + (size_t)row * DOUT + col) = hh;
                    __nv_bfloat162 ll;
                    ll.x = __float2bfloat16(v0 - __bfloat162float(h0));
                    ll.y = __float2bfloat16(v1 - __bfloat162float(h1));
                    *(__nv_bfloat162*)(Clo + (size_t)row * DOUT + col) = ll;
                }
            }
        }
    }
}

// ---------------------------------------------------------------------------
// Launch: detect(1) decode(2) split(3) gemm1(4=capture) scan fill
//         gather gemm2 gather gemm3
// ---------------------------------------------------------------------------
extern "C" void kernel_launch(void* const* d_in, const int* in_sizes, int n_in,
                              void* d_out, int out_size) {
    const float* x   = (const float*)d_in[0];
    const int*   ei  = (const int*)d_in[1];
    const float* W0  = (const float*)d_in[2];
    const float* b0  = (const float*)d_in[3];
    const float* Wl1 = (const float*)d_in[4];
    const float* bl1 = (const float*)d_in[5];
    const float* Wr1 = (const float*)d_in[6];
    const float* Wl2 = (const float*)d_in[7];
    const float* bl2 = (const float*)d_in[8];
    const float* Wr2 = (const float*)d_in[9];

    float* out1 = (float*)d_out;
    float* out2 = out1 + (size_t)NN * DOUT;

    float *h, *invdeg;
    int *degi, *off, *cur, *src, *dst, *csr;
    __nv_bfloat16 *xhi, *xlo, *w0hi, *w0lo, *wl1hi, *wl1lo, *wr1hi, *wr1lo;
    __nv_bfloat16 *wl2hi, *wl2lo, *wr2hi, *wr2lo, *hhi, *hlo, *mhi, *mlo, *o1hi, *o1lo;
    cudaGetSymbolAddress((void**)&h,      g_h);
    cudaGetSymbolAddress((void**)&invdeg, g_invdeg);
    cudaGetSymbolAddress((void**)&degi,   g_degi);
    cudaGetSymbolAddress((void**)&off,    g_off);
    cudaGetSymbolAddress((void**)&cur,    g_cur);
    cudaGetSymbolAddress((void**)&src,    g_src);
    cudaGetSymbolAddress((void**)&dst,    g_dst);
    cudaGetSymbolAddress((void**)&csr,    g_csr);
    cudaGetSymbolAddress((void**)&xhi,   g_xhi);   cudaGetSymbolAddress((void**)&xlo,   g_xlo);
    cudaGetSymbolAddress((void**)&w0hi,  g_w0hi);  cudaGetSymbolAddress((void**)&w0lo,  g_w0lo);
    cudaGetSymbolAddress((void**)&wl1hi, g_wl1hi); cudaGetSymbolAddress((void**)&wl1lo, g_wl1lo);
    cudaGetSymbolAddress((void**)&wr1hi, g_wr1hi); cudaGetSymbolAddress((void**)&wr1lo, g_wr1lo);
    cudaGetSymbolAddress((void**)&wl2hi, g_wl2hi); cudaGetSymbolAddress((void**)&wl2lo, g_wl2lo);
    cudaGetSymbolAddress((void**)&wr2hi, g_wr2hi); cudaGetSymbolAddress((void**)&wr2lo, g_wr2lo);
    cudaGetSymbolAddress((void**)&hhi,   g_hhi);   cudaGetSymbolAddress((void**)&hlo,   g_hlo);
    cudaGetSymbolAddress((void**)&mhi,   g_mhi);   cudaGetSymbolAddress((void**)&mlo,   g_mlo);
    cudaGetSymbolAddress((void**)&o1hi,  g_o1hi);  cudaGetSymbolAddress((void**)&o1lo,  g_o1lo);

    const int EB = (EE + 255) / 256;
    const int SPLIT_N = NN * DIN + DIN * DOUT + 4 * DOUT * DOUT;
    dim3 mgrid(DOUT / 64, (NN + 63) / 64);    // (4, 157) = 628 blocks

    detect_kernel<<<1, 256>>>(ei);                                     // k1
    cudaMemsetAsync(degi, 0, NN * sizeof(int));
    decode_degi_kernel<<<EB, 256>>>(ei, src, dst, degi);               // k2
    split_kernel<<<(SPLIT_N + 255) / 256, 256>>>(x, W0, Wl1, Wr1, Wl2, Wr2);  // k3

    // gemm1: h = x @ W0 + b0  (bf16x3: 3 passes, K=512) — k4, capture target
    {
        PassList P{};
        P.A[0] = xhi; P.W[0] = w0hi;
        P.A[1] = xlo; P.W[1] = w0hi;
        P.A[2] = xhi; P.W[2] = w0lo;
        gemm_mma<DIN, 3, false, false, true><<<mgrid, 256>>>(
            P, b0, nullptr, h, hhi, hlo, NN);
    }

    scan_kernel<<<1, 256>>>(degi, off, cur, invdeg);                   // k5
    fill_kernel<<<EB, 256>>>(src, dst, cur, csr);                      // k6

    // conv1
    gather_kernel<<<NN, 64>>>(h, csr, off, degi, invdeg, mhi, mlo);
    {
        PassList P{};
        P.A[0] = mhi; P.W[0] = wl1hi;
        P.A[1] = mlo; P.W[1] = wl1hi;
        P.A[2] = mhi; P.W[2] = wl1lo;
        P.A[3] = hhi; P.W[3] = wr1hi;
        P.A[4] = hlo; P.W[4] = wr1hi;
        P.A[5] = hhi; P.W[5] = wr1lo;
        gemm_mma<DOUT, 6, true, true, true><<<mgrid, 256>>>(
            P, bl1, h, out1, o1hi, o1lo, NN);
    }

    // conv2
    gather_kernel<<<NN, 64>>>(out1, csr, off, degi, invdeg, mhi, mlo);
    {
        PassList P{};
        P.A[0] = mhi;  P.W[0] = wl2hi;
        P.A[1] = mlo;  P.W[1] = wl2hi;
        P.A[2] = mhi;  P.W[2] = wl2lo;
        P.A[3] = o1hi; P.W[3] = wr2hi;
        P.A[4] = o1lo; P.W[4] = wr2hi;
        P.A[5] = o1hi; P.W[5] = wr2lo;
        gemm_mma<DOUT, 6, false, true, false><<<mgrid, 256>>>(
            P, bl2, out1, out2, nullptr, nullptr, NN);
    }
}